// round 1
// baseline (speedup 1.0000x reference)
#include <cuda_runtime.h>

// Problem: depthwise 3x3 conv over NHWC x[32,56,56,256], kernel[3,3,256] with
// center tap zeroed, plus residual add of x. Pure HBM-bound.
//
// Strategy: one thread per (b, h, channel-group-of-4). Thread slides along W
// keeping a 3x3 window of float4 in registers; 3 new float4 loads per output
// float4 (instead of 9) to stay under the LTS bandwidth cap. 64 consecutive
// threads cover one 1KB channel row -> fully coalesced 128B sectors.

#define Bn 32
#define Hn 56
#define Wn 56
#define C4 64   // 256 channels / 4 per float4

__device__ __forceinline__ float4 f4fma(float4 k, float4 v, float4 a) {
    a.x = fmaf(k.x, v.x, a.x);
    a.y = fmaf(k.y, v.y, a.y);
    a.z = fmaf(k.z, v.z, a.z);
    a.w = fmaf(k.w, v.w, a.w);
    return a;
}

__global__ __launch_bounds__(256)
void contour_integration_kernel(const float4* __restrict__ x,
                                const float4* __restrict__ k,
                                float4* __restrict__ out)
{
    const int c4 = threadIdx.x;                       // 0..63 channel group
    const int bh = blockIdx.x * 4 + threadIdx.y;      // 0..B*H-1
    const int b  = bh / Hn;
    const int h  = bh % Hn;

    // Kernel taps for this channel group (cross-correlation: k[i][j] hits
    // x[h-1+i, w-1+j]). Center tap k[1][1] is masked to zero -> skipped.
    const float4 k00 = __ldg(&k[0 * C4 + c4]);
    const float4 k01 = __ldg(&k[1 * C4 + c4]);
    const float4 k02 = __ldg(&k[2 * C4 + c4]);
    const float4 k10 = __ldg(&k[3 * C4 + c4]);
    const float4 k12 = __ldg(&k[5 * C4 + c4]);
    const float4 k20 = __ldg(&k[6 * C4 + c4]);
    const float4 k21 = __ldg(&k[7 * C4 + c4]);
    const float4 k22 = __ldg(&k[8 * C4 + c4]);

    const bool hm = (h > 0);
    const bool hp = (h < Hn - 1);

    const size_t base = ((size_t)b * Hn + h) * Wn * C4 + c4;
    const float4* __restrict__ row0 = x + base - (size_t)Wn * C4;  // h-1 (valid if hm)
    const float4* __restrict__ row1 = x + base;                    // h
    const float4* __restrict__ row2 = x + base + (size_t)Wn * C4;  // h+1 (valid if hp)
    float4* __restrict__ orow = out + base;

    const float4 Z = make_float4(0.f, 0.f, 0.f, 0.f);

    // Sliding window columns: a* = w-1, b* = w, n* = w+1  (rows h-1, h, h+1)
    float4 a0 = Z, a1 = Z, a2 = Z;
    float4 b0, b1, b2;
    float4 n0, n1, n2;

    b0 = hm ? __ldg(&row0[0]) : Z;
    b1 =      __ldg(&row1[0]);
    b2 = hp ? __ldg(&row2[0]) : Z;
    n0 = hm ? __ldg(&row0[C4]) : Z;
    n1 =      __ldg(&row1[C4]);
    n2 = hp ? __ldg(&row2[C4]) : Z;

    #pragma unroll 4
    for (int w = 0; w < Wn; ++w) {
        float4 acc = b1;                 // residual add (center x)
        acc = f4fma(k00, a0, acc);
        acc = f4fma(k01, b0, acc);
        acc = f4fma(k02, n0, acc);
        acc = f4fma(k10, a1, acc);
        acc = f4fma(k12, n1, acc);
        acc = f4fma(k20, a2, acc);
        acc = f4fma(k21, b2, acc);
        acc = f4fma(k22, n2, acc);

        orow[(size_t)w * C4] = acc;

        // shift window
        a0 = b0; a1 = b1; a2 = b2;
        b0 = n0; b1 = n1; b2 = n2;
        if (w + 2 < Wn) {
            const size_t off = (size_t)(w + 2) * C4;
            n0 = hm ? __ldg(&row0[off]) : Z;
            n1 =      __ldg(&row1[off]);
            n2 = hp ? __ldg(&row2[off]) : Z;
        } else {
            n0 = Z; n1 = Z; n2 = Z;
        }
    }
}

extern "C" void kernel_launch(void* const* d_in, const int* in_sizes, int n_in,
                              void* d_out, int out_size)
{
    const float4* x = (const float4*)d_in[0];   // [32,56,56,256] fp32
    const float4* k = (const float4*)d_in[1];   // [3,3,256] fp32
    float4* out = (float4*)d_out;

    dim3 block(64, 4);
    dim3 grid((Bn * Hn) / 4);   // 448 blocks
    contour_integration_kernel<<<grid, block>>>(x, k, out);
}

// round 2
// speedup vs baseline: 1.0398x; 1.0398x over previous
#include <cuda_runtime.h>

// Depthwise 3x3 (center tap zero) + residual over NHWC x[32,56,56,256] fp32.
// HBM-bound: floor ~206MB traffic. R1 lesson: float4 window cost 97 regs ->
// 21% occupancy -> DRAM only 34%. This version: float2 granularity (half the
// window/tap registers), half-row per thread, both halves of a row in one
// block. 128 threads x 8B = 1KB coalesced segments.

#define Bn 32
#define Hn 56
#define Wn 56
#define C2 128        // 256 channels / 2 per float2
#define SEG 28        // W split in halves

__device__ __forceinline__ float2 f2fma(float2 k, float2 v, float2 a) {
    a.x = fmaf(k.x, v.x, a.x);
    a.y = fmaf(k.y, v.y, a.y);
    return a;
}

__global__ __launch_bounds__(256, 4)
void contour_integration_kernel(const float2* __restrict__ x,
                                const float2* __restrict__ k,
                                float2* __restrict__ out)
{
    const int c2  = threadIdx.x;          // 0..127 channel pair
    const int seg = threadIdx.y;          // 0..1 half-row
    const int bh  = blockIdx.x;           // 0..B*H-1
    const int h   = bh % Hn;

    // taps (cross-correlation; center k[1][1] masked out)
    const float2 k00 = __ldg(&k[0 * C2 + c2]);
    const float2 k01 = __ldg(&k[1 * C2 + c2]);
    const float2 k02 = __ldg(&k[2 * C2 + c2]);
    const float2 k10 = __ldg(&k[3 * C2 + c2]);
    const float2 k12 = __ldg(&k[5 * C2 + c2]);
    const float2 k20 = __ldg(&k[6 * C2 + c2]);
    const float2 k21 = __ldg(&k[7 * C2 + c2]);
    const float2 k22 = __ldg(&k[8 * C2 + c2]);

    const bool hm = (h > 0);
    const bool hp = (h < Hn - 1);

    // 32-bit indexing: total float2 elements = 32*56*56*128 = 12.8M < 2^31
    const int base = (bh * Wn + seg * SEG) * C2 + c2;
    const float2* __restrict__ row0 = x + (base - Wn * C2);  // h-1 (if hm)
    const float2* __restrict__ row1 = x + base;              // h
    const float2* __restrict__ row2 = x + (base + Wn * C2);  // h+1 (if hp)
    float2* __restrict__ orow = out + base;

    const float2 Z = make_float2(0.f, 0.f);
    const int w0 = seg * SEG;

    // window columns: a=w-1, b=w, n=w+1 across rows h-1,h,h+1
    float2 a0, a1, a2, b0, b1, b2, n0, n1, n2;

    if (w0 == 0) {
        a0 = Z; a1 = Z; a2 = Z;
    } else {
        a0 = hm ? __ldg(&row0[-C2]) : Z;
        a1 =      __ldg(&row1[-C2]);
        a2 = hp ? __ldg(&row2[-C2]) : Z;
    }
    b0 = hm ? __ldg(&row0[0]) : Z;
    b1 =      __ldg(&row1[0]);
    b2 = hp ? __ldg(&row2[0]) : Z;
    n0 = hm ? __ldg(&row0[C2]) : Z;
    n1 =      __ldg(&row1[C2]);
    n2 = hp ? __ldg(&row2[C2]) : Z;

    #pragma unroll 4
    for (int i = 0; i < SEG; ++i) {
        float2 acc = b1;                       // residual
        acc = f2fma(k00, a0, acc);
        acc = f2fma(k01, b0, acc);
        acc = f2fma(k02, n0, acc);
        acc = f2fma(k10, a1, acc);
        acc = f2fma(k12, n1, acc);
        acc = f2fma(k20, a2, acc);
        acc = f2fma(k21, b2, acc);
        acc = f2fma(k22, n2, acc);

        orow[i * C2] = acc;

        // shift, prefetch column w0+i+2
        a0 = b0; a1 = b1; a2 = b2;
        b0 = n0; b1 = n1; b2 = n2;
        const int wn = w0 + i + 2;
        if (wn < Wn) {
            const int off = (i + 2) * C2;
            n0 = hm ? __ldg(&row0[off]) : Z;
            n1 =      __ldg(&row1[off]);
            n2 = hp ? __ldg(&row2[off]) : Z;
        } else {
            n0 = Z; n1 = Z; n2 = Z;
        }
    }
}

extern "C" void kernel_launch(void* const* d_in, const int* in_sizes, int n_in,
                              void* d_out, int out_size)
{
    const float2* x = (const float2*)d_in[0];   // [32,56,56,256] fp32
    const float2* k = (const float2*)d_in[1];   // [3,3,256] fp32
    float2* out = (float2*)d_out;

    dim3 block(C2, 2);           // 256 threads: full (b,h) row, two half-rows
    dim3 grid(Bn * Hn);          // 1792 blocks
    contour_integration_kernel<<<grid, block>>>(x, k, out);
}

// round 3
// speedup vs baseline: 1.7581x; 1.6908x over previous
#include <cuda_runtime.h>

// Depthwise 3x3 (center tap zero) + residual, NHWC x[32,56,56,256] fp32.
// R2 lesson: occupancy was not the limiter; per-warp load latency exposure was
// (load-use distance of 1 short iteration). This version: unroll-and-jam with
// batches of 4 outputs, 12 batched independent loads issued one full batch
// ahead of their use, all 14 batches fully unrolled (compile-time boundary
// guards, register-renamed window shifts), row predication replaced by
// zeroed taps + clamped row pointers.

#define Bn 32
#define Hn 56
#define Wn 56
#define C2 128   // 256 channels / 2 per float2

__device__ __forceinline__ float2 f2fma(float2 k, float2 v, float2 a) {
    a.x = fmaf(k.x, v.x, a.x);
    a.y = fmaf(k.y, v.y, a.y);
    return a;
}

__global__ __launch_bounds__(256, 3)
void contour_integration_kernel(const float2* __restrict__ x,
                                const float2* __restrict__ k,
                                float2* __restrict__ out)
{
    const int c2 = threadIdx.x;                    // 0..127 channel pair
    const int bh = blockIdx.x * 2 + threadIdx.y;   // 0..B*H-1
    const int h  = bh % Hn;

    const float2 Z = make_float2(0.f, 0.f);

    // taps (cross-correlation; center k[1][1] excluded)
    float2 k00 = __ldg(&k[0 * C2 + c2]);
    float2 k01 = __ldg(&k[1 * C2 + c2]);
    float2 k02 = __ldg(&k[2 * C2 + c2]);
    float2 k10 = __ldg(&k[3 * C2 + c2]);
    float2 k12 = __ldg(&k[5 * C2 + c2]);
    float2 k20 = __ldg(&k[6 * C2 + c2]);
    float2 k21 = __ldg(&k[7 * C2 + c2]);
    float2 k22 = __ldg(&k[8 * C2 + c2]);

    // boundary rows: zero the taps, clamp the pointer (loads stay valid,
    // contributions multiply to zero) -> all loads unconditional
    const bool hm = (h > 0);
    const bool hp = (h < Hn - 1);
    if (!hm) { k00 = Z; k01 = Z; k02 = Z; }
    if (!hp) { k20 = Z; k21 = Z; k22 = Z; }

    const int base = bh * Wn * C2 + c2;            // fits in 32 bits (12.8M max)
    const float2* __restrict__ row1 = x + base;
    const float2* __restrict__ row0 = hm ? (row1 - Wn * C2) : row1;
    const float2* __restrict__ row2 = hp ? (row1 + Wn * C2) : row1;
    float2* __restrict__ orow = out + base;

    // window: win[row][p], p=0..5 holds columns w-1..w+4 for batch start w
    float2 win[3][6];

    // prologue: col -1 = zero, load cols 0..4
    win[0][0] = Z; win[1][0] = Z; win[2][0] = Z;
    #pragma unroll
    for (int p = 1; p <= 5; ++p) {
        const int wc = p - 1;
        win[0][p] = __ldg(&row0[wc * C2]);
        win[1][p] = __ldg(&row1[wc * C2]);
        win[2][p] = __ldg(&row2[wc * C2]);
    }

    #pragma unroll
    for (int bidx = 0; bidx < 14; ++bidx) {
        const int w = bidx * 4;

        // compute 4 outputs w..w+3 (output w+j uses window positions j..j+2)
        #pragma unroll
        for (int j = 0; j < 4; ++j) {
            float2 acc = win[1][j + 1];            // residual (center x)
            acc = f2fma(k00, win[0][j],     acc);
            acc = f2fma(k01, win[0][j + 1], acc);
            acc = f2fma(k02, win[0][j + 2], acc);
            acc = f2fma(k10, win[1][j],     acc);
            acc = f2fma(k12, win[1][j + 2], acc);
            acc = f2fma(k20, win[2][j],     acc);
            acc = f2fma(k21, win[2][j + 1], acc);
            acc = f2fma(k22, win[2][j + 2], acc);
            orow[(w + j) * C2] = acc;
        }

        // shift window and batch-load the next 4 columns (for batch bidx+1)
        if (bidx < 13) {
            win[0][0] = win[0][4]; win[1][0] = win[1][4]; win[2][0] = win[2][4];
            win[0][1] = win[0][5]; win[1][1] = win[1][5]; win[2][1] = win[2][5];
            #pragma unroll
            for (int j = 0; j < 4; ++j) {
                const int wc = w + 5 + j;          // compile-time constant
                if (wc < Wn) {
                    win[0][2 + j] = __ldg(&row0[wc * C2]);
                    win[1][2 + j] = __ldg(&row1[wc * C2]);
                    win[2][2 + j] = __ldg(&row2[wc * C2]);
                } else {
                    win[0][2 + j] = Z;
                    win[1][2 + j] = Z;
                    win[2][2 + j] = Z;
                }
            }
        }
    }
}

extern "C" void kernel_launch(void* const* d_in, const int* in_sizes, int n_in,
                              void* d_out, int out_size)
{
    const float2* x = (const float2*)d_in[0];   // [32,56,56,256] fp32
    const float2* k = (const float2*)d_in[1];   // [3,3,256] fp32
    float2* out = (float2*)d_out;

    dim3 block(C2, 2);          // 256 threads: two full (b,h) rows per block
    dim3 grid(Bn * Hn / 2);     // 896 blocks
    contour_integration_kernel<<<grid, block>>>(x, k, out);
}